// round 9
// baseline (speedup 1.0000x reference)
#include <cuda_runtime.h>

// y[tok][o] = sum_e cos(x[tok][e] + theta[e]) * W[o][e],  E = 16, ntok = 1,048,576
//
// Warp handles 8 tokens/step (quad q owns token q; lane-slice i covers
// components/outputs [4i..4i+4)). Coalesced 512B warp loads/stores. W in
// registers (butterfly-permuted). z exchanged as packed f32x2 pairs via
// shfl.xor. Global loads software-pipelined one grid-stride group ahead.
// U=2 + launch_bounds(128,5): 20 warps/SM with prefetch in flight.

#define BLK 128
#define U   2
#define WPB (BLK / 32)

__device__ __forceinline__ unsigned long long pack2(float a, float b) {
    unsigned long long r;
    asm("mov.b64 %0, {%1, %2};" : "=l"(r) : "f"(a), "f"(b));
    return r;
}
__device__ __forceinline__ void unpack2(unsigned long long v, float& a, float& b) {
    asm("mov.b64 {%0, %1}, %2;" : "=f"(a), "=f"(b) : "l"(v));
}
__device__ __forceinline__ unsigned long long ffma2(unsigned long long a,
                                                    unsigned long long b,
                                                    unsigned long long c) {
    unsigned long long d;
    asm("fma.rn.f32x2 %0, %1, %2, %3;" : "=l"(d) : "l"(a), "l"(b), "l"(c));
    return d;
}
__device__ __forceinline__ unsigned long long fmul2(unsigned long long a,
                                                    unsigned long long b) {
    unsigned long long d;
    asm("mul.rn.f32x2 %0, %1, %2;" : "=l"(d) : "l"(a), "l"(b));
    return d;
}
__device__ __forceinline__ unsigned long long shflx64(unsigned long long v, int m) {
    return __shfl_xor_sync(0xFFFFFFFFu, v, m, 4);
}

__global__ __launch_bounds__(BLK, 5)
void qmha_kernel(const float4* __restrict__ x4,
                 const float* __restrict__ theta,
                 const float* __restrict__ w,      // [16][16] row-major w[o][e]
                 float4* __restrict__ out4,
                 int ntok)
{
    __shared__ float sW[256];

    const int tid  = threadIdx.x;
    const int lane = tid & 31;
    const int i    = lane & 3;    // slice within quad
    const int q    = lane >> 2;   // token within octet

    sW[tid * 2 + 0] = w[tid * 2 + 0];
    sW[tid * 2 + 1] = w[tid * 2 + 1];
    __syncthreads();

    // W packed by e-pairs in butterfly arrival order:
    //   slot s holds e-block b = i ^ s; h selects pair {4b+2h, 4b+2h+1};
    //   Wc[s][h][r] = { W[4i+r][4b+2h], W[4i+r][4b+2h+1] }
    unsigned long long Wc[4][2][4];
#pragma unroll
    for (int s = 0; s < 4; s++) {
        const int b = i ^ s;
#pragma unroll
        for (int h = 0; h < 2; h++) {
            const int e0 = 4 * b + 2 * h;
#pragma unroll
            for (int r = 0; r < 4; r++)
                Wc[s][h][r] = pack2(sW[(4 * i + r) * 16 + e0],
                                    sW[(4 * i + r) * 16 + e0 + 1]);
        }
    }
    const float4 th = reinterpret_cast<const float4*>(theta)[i];

    const int warp_id = blockIdx.x * WPB + (tid >> 5);
    const int nwarps  = gridDim.x * WPB;
    const int noct    = (ntok + 7) >> 3;
    const int ngrp    = (noct + U - 1) / U;

    // ---- prologue: load group g0 ----
    int g = warp_id;
    float4 xv[U];
    if (g < ngrp) {
        const int oct0 = g * U;
        const bool full = (oct0 * 8 + U * 8) <= ntok;
#pragma unroll
        for (int u = 0; u < U; u++) {
            const int tok = (oct0 + u) * 8 + q;
            xv[u] = (full || tok < ntok)
                      ? __ldcs(&x4[(size_t)(oct0 + u) * 32 + lane])
                      : make_float4(0.f, 0.f, 0.f, 0.f);
        }
    }

    for (; g < ngrp; ) {
        const int gn = g + nwarps;

        // ---- prefetch next group (issued before any compute; consumed next iter)
        float4 xn[U];
        if (gn < ngrp) {
            const int oct0n = gn * U;
            const bool fulln = (oct0n * 8 + U * 8) <= ntok;
#pragma unroll
            for (int u = 0; u < U; u++) {
                const int tok = (oct0n + u) * 8 + q;
                xn[u] = (fulln || tok < ntok)
                          ? __ldcs(&x4[(size_t)(oct0n + u) * 32 + lane])
                          : make_float4(0.f, 0.f, 0.f, 0.f);
            }
        }

        // ---- compute + store current group
        const int oct0 = g * U;
        const bool full = (oct0 * 8 + U * 8) <= ntok;
#pragma unroll
        for (int u = 0; u < U; u++) {
            const unsigned long long p0 = pack2(__cosf(xv[u].x + th.x),
                                                __cosf(xv[u].y + th.y));
            const unsigned long long p1 = pack2(__cosf(xv[u].z + th.z),
                                                __cosf(xv[u].w + th.w));

            const unsigned long long q0 = shflx64(p0, 1);
            const unsigned long long q1 = shflx64(p1, 1);

            unsigned long long acc[4];
#pragma unroll
            for (int r = 0; r < 4; r++) {
                acc[r] = fmul2(p0, Wc[0][0][r]);
                acc[r] = ffma2(p1, Wc[0][1][r], acc[r]);
            }

            const unsigned long long r0 = shflx64(p0, 2);
            const unsigned long long r1 = shflx64(p1, 2);
#pragma unroll
            for (int r = 0; r < 4; r++) {
                acc[r] = ffma2(q0, Wc[1][0][r], acc[r]);
                acc[r] = ffma2(q1, Wc[1][1][r], acc[r]);
            }

            const unsigned long long s0 = shflx64(q0, 2);
            const unsigned long long s1 = shflx64(q1, 2);
#pragma unroll
            for (int r = 0; r < 4; r++) {
                acc[r] = ffma2(r0, Wc[2][0][r], acc[r]);
                acc[r] = ffma2(r1, Wc[2][1][r], acc[r]);
            }
#pragma unroll
            for (int r = 0; r < 4; r++) {
                acc[r] = ffma2(s0, Wc[3][0][r], acc[r]);
                acc[r] = ffma2(s1, Wc[3][1][r], acc[r]);
            }

            float4 yv;
            {
                float a, b;
                unpack2(acc[0], a, b); yv.x = a + b;
                unpack2(acc[1], a, b); yv.y = a + b;
                unpack2(acc[2], a, b); yv.z = a + b;
                unpack2(acc[3], a, b); yv.w = a + b;
            }

            if (full || ((oct0 + u) * 8 + q) < ntok)
                __stcs(&out4[(size_t)(oct0 + u) * 32 + lane], yv);
        }

        // ---- rotate buffers
        g = gn;
#pragma unroll
        for (int u = 0; u < U; u++) xv[u] = xn[u];
    }
}

extern "C" void kernel_launch(void* const* d_in, const int* in_sizes, int n_in,
                              void* d_out, int out_size) {
    const float* x     = (const float*)d_in[0];   // [B, S, 16] f32
    const float* theta = (const float*)d_in[1];   // [16] f32
    const float* w     = (const float*)d_in[2];   // [16, 16] f32
    float* out         = (float*)d_out;           // [B, S, 16] f32

    const int ntok = in_sizes[0] / 16;

    const int noct = (ntok + 7) >> 3;
    const int ngrp = (noct + U - 1) / U;
    int blocks = (ngrp + WPB - 1) / WPB;
    const int cap = 148 * 5;   // single resident wave at 5 blocks/SM
    if (blocks > cap) blocks = cap;

    qmha_kernel<<<blocks, BLK>>>((const float4*)x, theta, w, (float4*)out, ntok);
}

// round 10
// speedup vs baseline: 2.2993x; 2.2993x over previous
#include <cuda_runtime.h>

// y[tok][o] = sum_e cos(x[tok][e] + theta[e]) * W[o][e],  E = 16, ntok = 1,048,576
//
// Warp handles 8 tokens/step (quad q owns token q; lane-slice i covers
// components/outputs [4i..4i+4)). Coalesced 512B warp loads/stores. W in
// registers (butterfly-permuted). z exchanged as packed f32x2 pairs via
// shfl.xor. Next grid-stride group is prefetched INTO L2 (prefetch.global.L2,
// zero register cost); consume loads then see ~L2 latency, covered by the
// 4-octet compute body.

#define BLK 128
#define U   4
#define WPB (BLK / 32)

__device__ __forceinline__ unsigned long long pack2(float a, float b) {
    unsigned long long r;
    asm("mov.b64 %0, {%1, %2};" : "=l"(r) : "f"(a), "f"(b));
    return r;
}
__device__ __forceinline__ void unpack2(unsigned long long v, float& a, float& b) {
    asm("mov.b64 {%0, %1}, %2;" : "=f"(a), "=f"(b) : "l"(v));
}
__device__ __forceinline__ unsigned long long ffma2(unsigned long long a,
                                                    unsigned long long b,
                                                    unsigned long long c) {
    unsigned long long d;
    asm("fma.rn.f32x2 %0, %1, %2, %3;" : "=l"(d) : "l"(a), "l"(b), "l"(c));
    return d;
}
__device__ __forceinline__ unsigned long long fmul2(unsigned long long a,
                                                    unsigned long long b) {
    unsigned long long d;
    asm("mul.rn.f32x2 %0, %1, %2;" : "=l"(d) : "l"(a), "l"(b));
    return d;
}
__device__ __forceinline__ unsigned long long shflx64(unsigned long long v, int m) {
    return __shfl_xor_sync(0xFFFFFFFFu, v, m, 4);
}
__device__ __forceinline__ void prefetch_l2(const void* p) {
    asm volatile("prefetch.global.L2 [%0];" :: "l"(p));
}

__global__ __launch_bounds__(BLK, 4)
void qmha_kernel(const float4* __restrict__ x4,
                 const float* __restrict__ theta,
                 const float* __restrict__ w,      // [16][16] row-major w[o][e]
                 float4* __restrict__ out4,
                 int ntok)
{
    __shared__ float sW[256];

    const int tid  = threadIdx.x;
    const int lane = tid & 31;
    const int i    = lane & 3;    // slice within quad
    const int q    = lane >> 2;   // token within octet

    sW[tid * 2 + 0] = w[tid * 2 + 0];
    sW[tid * 2 + 1] = w[tid * 2 + 1];
    __syncthreads();

    // W packed by e-pairs in butterfly arrival order:
    //   slot s holds e-block b = i ^ s; h selects pair {4b+2h, 4b+2h+1};
    //   Wc[s][h][r] = { W[4i+r][4b+2h], W[4i+r][4b+2h+1] }
    unsigned long long Wc[4][2][4];
#pragma unroll
    for (int s = 0; s < 4; s++) {
        const int b = i ^ s;
#pragma unroll
        for (int h = 0; h < 2; h++) {
            const int e0 = 4 * b + 2 * h;
#pragma unroll
            for (int r = 0; r < 4; r++)
                Wc[s][h][r] = pack2(sW[(4 * i + r) * 16 + e0],
                                    sW[(4 * i + r) * 16 + e0 + 1]);
        }
    }
    const float4 th = reinterpret_cast<const float4*>(theta)[i];

    const int warp_id = blockIdx.x * WPB + (tid >> 5);
    const int nwarps  = gridDim.x * WPB;
    const int noct    = (ntok + 7) >> 3;
    const int ngrp    = (noct + U - 1) / U;

    for (int g = warp_id; g < ngrp; g += nwarps) {
        const int oct0 = g * U;
        const bool full = (oct0 * 8 + U * 8) <= ntok;

        // ---- load current group (should hit L2 thanks to prefetch last iter)
        float4 xv[U];
        if (full) {
#pragma unroll
            for (int u = 0; u < U; u++)
                xv[u] = __ldcs(&x4[(size_t)(oct0 + u) * 32 + lane]);
        } else {
#pragma unroll
            for (int u = 0; u < U; u++) {
                const int tok = (oct0 + u) * 8 + q;
                xv[u] = (tok < ntok) ? __ldcs(&x4[(size_t)(oct0 + u) * 32 + lane])
                                     : make_float4(0.f, 0.f, 0.f, 0.f);
            }
        }

        // ---- prefetch next group into L2 (zero register cost)
        const int gn = g + nwarps;
        if (gn < ngrp) {
            const int oct0n = gn * U;
#pragma unroll
            for (int u = 0; u < U; u++)
                prefetch_l2(&x4[(size_t)(oct0n + u) * 32 + lane]);
        }

        // ---- compute + store current group
#pragma unroll
        for (int u = 0; u < U; u++) {
            const unsigned long long p0 = pack2(__cosf(xv[u].x + th.x),
                                                __cosf(xv[u].y + th.y));
            const unsigned long long p1 = pack2(__cosf(xv[u].z + th.z),
                                                __cosf(xv[u].w + th.w));

            const unsigned long long q0 = shflx64(p0, 1);
            const unsigned long long q1 = shflx64(p1, 1);

            unsigned long long acc[4];
#pragma unroll
            for (int r = 0; r < 4; r++) {
                acc[r] = fmul2(p0, Wc[0][0][r]);
                acc[r] = ffma2(p1, Wc[0][1][r], acc[r]);
            }

            const unsigned long long r0 = shflx64(p0, 2);
            const unsigned long long r1 = shflx64(p1, 2);
#pragma unroll
            for (int r = 0; r < 4; r++) {
                acc[r] = ffma2(q0, Wc[1][0][r], acc[r]);
                acc[r] = ffma2(q1, Wc[1][1][r], acc[r]);
            }

            const unsigned long long s0 = shflx64(q0, 2);
            const unsigned long long s1 = shflx64(q1, 2);
#pragma unroll
            for (int r = 0; r < 4; r++) {
                acc[r] = ffma2(r0, Wc[2][0][r], acc[r]);
                acc[r] = ffma2(r1, Wc[2][1][r], acc[r]);
            }
#pragma unroll
            for (int r = 0; r < 4; r++) {
                acc[r] = ffma2(s0, Wc[3][0][r], acc[r]);
                acc[r] = ffma2(s1, Wc[3][1][r], acc[r]);
            }

            float4 yv;
            {
                float a, b;
                unpack2(acc[0], a, b); yv.x = a + b;
                unpack2(acc[1], a, b); yv.y = a + b;
                unpack2(acc[2], a, b); yv.z = a + b;
                unpack2(acc[3], a, b); yv.w = a + b;
            }

            if (full || ((oct0 + u) * 8 + q) < ntok)
                __stcs(&out4[(size_t)(oct0 + u) * 32 + lane], yv);
        }
    }
}

extern "C" void kernel_launch(void* const* d_in, const int* in_sizes, int n_in,
                              void* d_out, int out_size) {
    const float* x     = (const float*)d_in[0];   // [B, S, 16] f32
    const float* theta = (const float*)d_in[1];   // [16] f32
    const float* w     = (const float*)d_in[2];   // [16, 16] f32
    float* out         = (float*)d_out;           // [B, S, 16] f32

    const int ntok = in_sizes[0] / 16;

    const int noct = (ntok + 7) >> 3;
    const int ngrp = (noct + U - 1) / U;
    int blocks = (ngrp + WPB - 1) / WPB;
    const int cap = 148 * 4;   // single resident wave at 4 blocks/SM (R7's known-good shape)
    if (blocks > cap) blocks = cap;

    qmha_kernel<<<blocks, BLK>>>((const float4*)x, theta, w, (float4*)out, ntok);
}